// round 10
// baseline (speedup 1.0000x reference)
#include <cuda_runtime.h>
#include <cuda_bf16.h>

#define EPS     1e-5f
#define THREADS 256
#define TILE_M  128
#define NPTS    (64 * 1024)
#define NBLK    (NPTS / TILE_M)   // 512 CTAs

// ---- pre-folded weights in ldmatrix-ready layout ----
// Per (j,t) a 512B block: [hi k0-7][hi k8-15][lo k0-7][lo k8-15], each 8x8 bf16 tile
// row n = output (o&7), 16B/row. W1 @0 (KT=2, 8192B), W2 @8192, W3 @24576 (KT=4, 16384B each).
__device__ __align__(16) char  wbuf[40960];
__device__ __align__(16) float bbuf[192];

typedef unsigned long long ull;

// ---- packed fp32x2 helpers ----
__device__ __forceinline__ ull fma2(ull a, ull b, ull c) {
    ull d; asm("fma.rn.f32x2 %0,%1,%2,%3;" : "=l"(d) : "l"(a), "l"(b), "l"(c)); return d;
}
__device__ __forceinline__ ull mul2(ull a, ull b) {
    ull d; asm("mul.rn.f32x2 %0,%1,%2;" : "=l"(d) : "l"(a), "l"(b)); return d;
}
__device__ __forceinline__ void unpk(ull v, float& lo, float& hi) {
    asm("mov.b64 {%0,%1}, %2;" : "=f"(lo), "=f"(hi) : "l"(v));
}
__device__ __forceinline__ ull pk2(float lo, float hi) {
    ull v; asm("mov.b64 %0, {%1,%2};" : "=l"(v) : "f"(lo), "f"(hi)); return v;
}
__device__ __forceinline__ ull pkc(float c) {
    unsigned u = __float_as_uint(c); return ((ull)u << 32) | (ull)u;
}
__device__ __forceinline__ float frcp(float x) {
    float r; asm("rcp.approx.f32 %0,%1;" : "=f"(r) : "f"(x)); return r;
}

// Exact-class GELU on a packed pair via A&S 7.1.28 (|erf err|<=3e-7, branch-free):
// gelu(x) = 0.5x + 0.5|x|(1 - d^-16), d = 1 + a1 z + ... + a6 z^6, z = |x|/sqrt2.
__device__ __forceinline__ ull gelu2(ull s) {
    const ull C_ISQ2 = pkc(0.70710678118654752f);
    ull z = mul2(s & 0x7FFFFFFF7FFFFFFFULL, C_ISQ2);
    ull d = fma2(z, pkc(0.0000430638f), pkc(0.0002765672f));
    d = fma2(z, d, pkc(0.0001520143f));
    d = fma2(z, d, pkc(0.0092705272f));
    d = fma2(z, d, pkc(0.0422820123f));
    d = fma2(z, d, pkc(0.0705230784f));
    d = fma2(z, d, pkc(1.0f));
    d = mul2(d, d); d = mul2(d, d); d = mul2(d, d); d = mul2(d, d);   // d^16
    float dl, dh; unpk(d, dl, dh);
    ull r = pk2(frcp(dl), frcp(dh));                                  // d^-16
    ull u = mul2(z, C_ISQ2);                                          // 0.5|x|
    ull w = fma2(r ^ 0x8000000080000000ULL, u, u);                    // u(1-r)
    return fma2(s, pkc(0.5f), w);
}

// packed f32 pair -> (bf16x2 hi, bf16x2 lo-residual)
__device__ __forceinline__ void splitpair(ull v, unsigned& hb, unsigned& lb) {
    float f0, f1; unpk(v, f0, f1);
    unsigned h;
    asm("cvt.rn.bf16x2.f32 %0, %1, %2;" : "=r"(h) : "f"(f1), "f"(f0));
    float a0 = __uint_as_float(h << 16);
    float a1 = __uint_as_float(h & 0xFFFF0000u);
    float r0 = f0 - a0, r1 = f1 - a1;
    unsigned l;
    asm("cvt.rn.bf16x2.f32 %0, %1, %2;" : "=r"(l) : "f"(r1), "f"(r0));
    hb = h; lb = l;
}

// D += A(m16k16 bf16, row) @ B(k16n8 bf16, col); fp32 accum. Baseline PTX (sm_80+).
__device__ __forceinline__ void mma16816(float d[4], const unsigned a[4],
                                         unsigned b0, unsigned b1) {
    asm volatile(
        "mma.sync.aligned.m16n8k16.row.col.f32.bf16.bf16.f32 "
        "{%0,%1,%2,%3},{%4,%5,%6,%7},{%8,%9},{%0,%1,%2,%3};"
        : "+f"(d[0]), "+f"(d[1]), "+f"(d[2]), "+f"(d[3])
        : "r"(a[0]), "r"(a[1]), "r"(a[2]), "r"(a[3]), "r"(b0), "r"(b1));
}

__device__ __forceinline__ unsigned smem_u32(const void* p) {
    unsigned a;
    asm("{.reg .u64 t; cvta.to.shared.u64 t, %1; cvt.u32.u64 %0, t;}" : "=r"(a) : "l"(p));
    return a;
}

// ldmatrix-layout offset for hi element (o,k); lo = +256
template<int KT>
__device__ __forceinline__ int woff_lm(int o, int k) {
    int j = o >> 3, n = o & 7, t = k >> 4, kk = k & 15, h8 = kk >> 3, c = kk & 7;
    return (j * KT + t) * 512 + h8 * 128 + n * 16 + c * 2;
}

// ---- one-shot fold kernel: BN-fold + bf16 hi/lo split into ldmatrix tile layout ----
__global__ void fold_kernel(
    const float* __restrict__ W1, const float* __restrict__ g1, const float* __restrict__ b1,
    const float* __restrict__ m1, const float* __restrict__ v1,
    const float* __restrict__ W2, const float* __restrict__ g2, const float* __restrict__ b2,
    const float* __restrict__ m2, const float* __restrict__ v2,
    const float* __restrict__ W3, const float* __restrict__ g3, const float* __restrict__ b3,
    const float* __restrict__ m3, const float* __restrict__ v3)
{
    int i = blockIdx.x * blockDim.x + threadIdx.x;
    if (i < 2048) {                               // W1 [64x32]
        int o = i >> 5, k = i & 31;
        float w = W1[i] * (g1[o] * rsqrtf(v1[o] + EPS));
        __nv_bfloat16 hi = __float2bfloat16(w);
        int off = woff_lm<2>(o, k);
        *(__nv_bfloat16*)(wbuf + off)       = hi;
        *(__nv_bfloat16*)(wbuf + off + 256) = __float2bfloat16(w - __bfloat162float(hi));
    } else if (i < 2048 + 4096) {                 // W2 [64x64]
        int j = i - 2048, o = j >> 6, k = j & 63;
        float w = W2[j] * (g2[o] * rsqrtf(v2[o] + EPS));
        __nv_bfloat16 hi = __float2bfloat16(w);
        int off = 8192 + woff_lm<4>(o, k);
        *(__nv_bfloat16*)(wbuf + off)       = hi;
        *(__nv_bfloat16*)(wbuf + off + 256) = __float2bfloat16(w - __bfloat162float(hi));
    } else if (i < 2048 + 8192) {                 // W3 [64x64]
        int j = i - 6144, o = j >> 6, k = j & 63;
        float w = W3[j] * (g3[o] * rsqrtf(v3[o] + EPS));
        __nv_bfloat16 hi = __float2bfloat16(w);
        int off = 24576 + woff_lm<4>(o, k);
        *(__nv_bfloat16*)(wbuf + off)       = hi;
        *(__nv_bfloat16*)(wbuf + off + 256) = __float2bfloat16(w - __bfloat162float(hi));
    }
    if (i < 64) {
        bbuf[i]       = b1[i] - m1[i] * (g1[i] * rsqrtf(v1[i] + EPS));
        bbuf[64 + i]  = b2[i] - m2[i] * (g2[i] * rsqrtf(v2[i] + EPS));
        bbuf[128 + i] = b3[i] - m3[i] * (g3[i] * rsqrtf(v3[i] + EPS));
    }
}

// One GEMM stage (per warp, one 16-row m-tile), bias pre-loaded into accumulators:
// D[8][4] = bias + (Ah+Al)@(Wh+Wl)^T, dropping lo*lo. One LDSM.x4 per (j,t).
template<int KT>
__device__ __forceinline__ void run_stage(unsigned wp, const float* bias,
                                          unsigned Ah[4][4], unsigned Al[4][4],
                                          float D[8][4], int p) {
    #pragma unroll
    for (int j = 0; j < 8; ++j) {
        float b0, b1;
        unpk(*(const ull*)(bias + 8 * j + 2 * p), b0, b1);
        D[j][0] = b0; D[j][1] = b1; D[j][2] = b0; D[j][3] = b1;
        #pragma unroll
        for (int t = 0; t < KT; ++t) {
            unsigned bh0, bh1, bl0, bl1;
            asm volatile(
                "ldmatrix.sync.aligned.m8n8.x4.shared.b16 {%0,%1,%2,%3}, [%4];"
                : "=r"(bh0), "=r"(bh1), "=r"(bl0), "=r"(bl1) : "r"(wp));
            wp += 512;
            mma16816(D[j], Ah[t], bh0, bh1);   // hi*hi
            mma16816(D[j], Ah[t], bl0, bl1);   // hi*lo
            mma16816(D[j], Al[t], bh0, bh1);   // lo*hi
        }
    }
}

// gelu + re-split into next stage's A fragments (pure per-thread register work)
__device__ __forceinline__ void epilogue_mid(float D[8][4],
                                             unsigned Ah[4][4], unsigned Al[4][4]) {
    #pragma unroll
    for (int j = 0; j < 8; ++j) {
        int t = j >> 1;
        int rb = (j & 1) ? 2 : 0;
        ull v0 = gelu2(pk2(D[j][0], D[j][1]));
        ull v1 = gelu2(pk2(D[j][2], D[j][3]));
        splitpair(v0, Ah[t][rb],     Al[t][rb]);
        splitpair(v1, Ah[t][rb + 1], Al[t][rb + 1]);
    }
}

__global__ void __launch_bounds__(THREADS, 2) mlp_mma_kernel(
    const float* __restrict__ x, float* __restrict__ out)
{
    __shared__ __align__(16) float sbias[256];
    __shared__ __align__(16) char  sw[40960];
    const int tid = threadIdx.x;
    const int lane = tid & 31, wid = tid >> 5;   // warp = one 16-row m-tile
    const int g = lane >> 2, p = lane & 3;

    // ---- prologue: flat copy of pre-folded weights + biases into SMEM ----
    {
        const uint4* src = (const uint4*)wbuf;
        uint4* dst = (uint4*)sw;
        #pragma unroll
        for (int i = 0; i < 10; ++i) dst[tid + i * THREADS] = src[tid + i * THREADS];
        if (tid < 48) ((uint4*)sbias)[tid] = ((const uint4*)bbuf)[tid];
    }

    // ---- build stage-1 A fragments straight from GMEM (no staging) ----
    const int pbase = blockIdx.x * TILE_M;
    unsigned Ah[4][4], Al[4][4];
    {
        const float* xr = x + (size_t)(pbase + wid * 16 + g) * 32;   // row g; row g+8 = +256
        #pragma unroll
        for (int t = 0; t < 2; ++t) {
            int c0 = p * 2 + t * 16;
            splitpair(*(const ull*)(xr + c0),           Ah[t][0], Al[t][0]);
            splitpair(*(const ull*)(xr + 256 + c0),     Ah[t][1], Al[t][1]);
            splitpair(*(const ull*)(xr + c0 + 8),       Ah[t][2], Al[t][2]);
            splitpair(*(const ull*)(xr + 256 + c0 + 8), Ah[t][3], Al[t][3]);
        }
    }
    __syncthreads();

    const unsigned wbase = smem_u32(sw) + lane * 16;   // ldmatrix lane address
    float D[8][4];

    run_stage<2>(wbase,         sbias,       Ah, Al, D, p);
    epilogue_mid(D, Ah, Al);

    run_stage<4>(wbase + 8192,  sbias + 64,  Ah, Al, D, p);
    epilogue_mid(D, Ah, Al);

    run_stage<4>(wbase + 24576, sbias + 128, Ah, Al, D, p);

    // ---- final: gelu -> direct transposed STG (4x32B segments per warp-instr) ----
    float* ob = out + (size_t)(pbase >> 10) * 65536 + (pbase & 1023) + wid * 16 + g;
    #pragma unroll
    for (int j = 0; j < 8; ++j) {
        int o0 = 8 * j + 2 * p;
        ull v0 = gelu2(pk2(D[j][0], D[j][1]));   // cols o0,o0+1 @ row g
        ull v1 = gelu2(pk2(D[j][2], D[j][3]));   // cols o0,o0+1 @ row g+8
        float f0, f1;
        unpk(v0, f0, f1);
        ob[(size_t)o0 * 1024]       = f0;
        ob[(size_t)(o0 + 1) * 1024] = f1;
        unpk(v1, f0, f1);
        ob[(size_t)o0 * 1024 + 8]       = f0;
        ob[(size_t)(o0 + 1) * 1024 + 8] = f1;
    }
}

extern "C" void kernel_launch(void* const* d_in, const int* in_sizes, int n_in,
                              void* d_out, int out_size)
{
    const float* x  = (const float*)d_in[0];
    const float* W1 = (const float*)d_in[1];
    const float* g1 = (const float*)d_in[2];
    const float* b1 = (const float*)d_in[3];
    const float* m1 = (const float*)d_in[4];
    const float* v1 = (const float*)d_in[5];
    const float* W2 = (const float*)d_in[6];
    const float* g2 = (const float*)d_in[7];
    const float* b2 = (const float*)d_in[8];
    const float* m2 = (const float*)d_in[9];
    const float* v2 = (const float*)d_in[10];
    const float* W3 = (const float*)d_in[11];
    const float* g3 = (const float*)d_in[12];
    const float* b3 = (const float*)d_in[13];
    const float* m3 = (const float*)d_in[14];
    const float* v3 = (const float*)d_in[15];
    float* out = (float*)d_out;

    fold_kernel<<<40, 256>>>(W1, g1, b1, m1, v1, W2, g2, b2, m2, v2, W3, g3, b3, m3, v3);
    mlp_mma_kernel<<<NBLK, THREADS>>>(x, out);
}

// round 11
// speedup vs baseline: 1.0918x; 1.0918x over previous
#include <cuda_runtime.h>
#include <cuda_bf16.h>

#define EPS     1e-5f
#define THREADS 256
#define TILE_M  128
#define NPTS    (64 * 1024)
#define NBLK    (NPTS / TILE_M)   // 512 CTAs

// ---- pre-folded weights: bf16 hi|lo interleaved per 16B unit, fragment layout ----
// W1 @0 (8192B, KT=2), W2 @8192 (16384B, KT=4), W3 @24576 (16384B, KT=4)
__device__ __align__(16) char  wbuf[40960];
__device__ __align__(16) float bbuf[192];

typedef unsigned long long ull;

// ---- packed fp32x2 helpers ----
__device__ __forceinline__ ull fma2(ull a, ull b, ull c) {
    ull d; asm("fma.rn.f32x2 %0,%1,%2,%3;" : "=l"(d) : "l"(a), "l"(b), "l"(c)); return d;
}
__device__ __forceinline__ ull mul2(ull a, ull b) {
    ull d; asm("mul.rn.f32x2 %0,%1,%2;" : "=l"(d) : "l"(a), "l"(b)); return d;
}
__device__ __forceinline__ void unpk(ull v, float& lo, float& hi) {
    asm("mov.b64 {%0,%1}, %2;" : "=f"(lo), "=f"(hi) : "l"(v));
}
__device__ __forceinline__ ull pk2(float lo, float hi) {
    ull v; asm("mov.b64 %0, {%1,%2};" : "=l"(v) : "f"(lo), "f"(hi)); return v;
}
__device__ __forceinline__ ull pkc(float c) {
    unsigned u = __float_as_uint(c); return ((ull)u << 32) | (ull)u;
}
__device__ __forceinline__ float frcp(float x) {
    float r; asm("rcp.approx.f32 %0,%1;" : "=f"(r) : "f"(x)); return r;
}

// Exact-class GELU on a packed pair via A&S 7.1.28 (|erf err|<=3e-7, branch-free):
// gelu(x) = 0.5x + 0.5|x|(1 - d^-16), d = 1 + a1 z + ... + a6 z^6, z = |x|/sqrt2.
__device__ __forceinline__ ull gelu2(ull s) {
    const ull C_ISQ2 = pkc(0.70710678118654752f);
    ull z = mul2(s & 0x7FFFFFFF7FFFFFFFULL, C_ISQ2);
    ull d = fma2(z, pkc(0.0000430638f), pkc(0.0002765672f));
    d = fma2(z, d, pkc(0.0001520143f));
    d = fma2(z, d, pkc(0.0092705272f));
    d = fma2(z, d, pkc(0.0422820123f));
    d = fma2(z, d, pkc(0.0705230784f));
    d = fma2(z, d, pkc(1.0f));
    d = mul2(d, d); d = mul2(d, d); d = mul2(d, d); d = mul2(d, d);   // d^16
    float dl, dh; unpk(d, dl, dh);
    ull r = pk2(frcp(dl), frcp(dh));                                  // d^-16
    ull u = mul2(z, C_ISQ2);                                          // 0.5|x|
    ull w = fma2(r ^ 0x8000000080000000ULL, u, u);                    // u(1-r)
    return fma2(s, pkc(0.5f), w);
}

// packed f32 pair -> (bf16x2 hi, bf16x2 lo-residual)
__device__ __forceinline__ void splitpair(ull v, unsigned& hb, unsigned& lb) {
    float f0, f1; unpk(v, f0, f1);
    unsigned h;
    asm("cvt.rn.bf16x2.f32 %0, %1, %2;" : "=r"(h) : "f"(f1), "f"(f0));
    float a0 = __uint_as_float(h << 16);
    float a1 = __uint_as_float(h & 0xFFFF0000u);
    float r0 = f0 - a0, r1 = f1 - a1;
    unsigned l;
    asm("cvt.rn.bf16x2.f32 %0, %1, %2;" : "=r"(l) : "f"(r1), "f"(r0));
    hb = h; lb = l;
}

// D += A(m16k16 bf16, row) @ B(k16n8 bf16, col); fp32 accum. Baseline PTX (sm_80+).
__device__ __forceinline__ void mma16816(float d[4], const unsigned a[4],
                                         unsigned b0, unsigned b1) {
    asm volatile(
        "mma.sync.aligned.m16n8k16.row.col.f32.bf16.bf16.f32 "
        "{%0,%1,%2,%3},{%4,%5,%6,%7},{%8,%9},{%0,%1,%2,%3};"
        : "+f"(d[0]), "+f"(d[1]), "+f"(d[2]), "+f"(d[3])
        : "r"(a[0]), "r"(a[1]), "r"(a[2]), "r"(a[3]), "r"(b0), "r"(b1));
}

// 16B unit(o,t,p): bytes[0,8)=hi frag {k=16t+2p,+1,+8,+9}, bytes[8,16)=lo frag.
// t XOR-swizzled -> 8-lane LDS.128 phases are bank-conflict-free.
template<int KT>
__device__ __forceinline__ int woff16(int o, int k) {
    int t = k >> 4, kk = k & 15, pp = (kk & 7) >> 1, half = kk >> 3;
    int ts = t ^ (o & (KT - 1));
    return ((o * KT + ts) * 4 + pp) * 16 + half * 4 + (k & 1) * 2;
}

// ---- one-shot fold kernel: BN-fold + bf16 hi/lo split into interleaved fragment layout ----
__global__ void fold_kernel(
    const float* __restrict__ W1, const float* __restrict__ g1, const float* __restrict__ b1,
    const float* __restrict__ m1, const float* __restrict__ v1,
    const float* __restrict__ W2, const float* __restrict__ g2, const float* __restrict__ b2,
    const float* __restrict__ m2, const float* __restrict__ v2,
    const float* __restrict__ W3, const float* __restrict__ g3, const float* __restrict__ b3,
    const float* __restrict__ m3, const float* __restrict__ v3)
{
    int i = blockIdx.x * blockDim.x + threadIdx.x;
    if (i < 2048) {                               // W1 [64x32]
        int o = i >> 5, k = i & 31;
        float w = W1[i] * (g1[o] * rsqrtf(v1[o] + EPS));
        __nv_bfloat16 hi = __float2bfloat16(w);
        int off = woff16<2>(o, k);
        *(__nv_bfloat16*)(wbuf + off)     = hi;
        *(__nv_bfloat16*)(wbuf + off + 8) = __float2bfloat16(w - __bfloat162float(hi));
    } else if (i < 2048 + 4096) {                 // W2 [64x64]
        int j = i - 2048, o = j >> 6, k = j & 63;
        float w = W2[j] * (g2[o] * rsqrtf(v2[o] + EPS));
        __nv_bfloat16 hi = __float2bfloat16(w);
        int off = 8192 + woff16<4>(o, k);
        *(__nv_bfloat16*)(wbuf + off)     = hi;
        *(__nv_bfloat16*)(wbuf + off + 8) = __float2bfloat16(w - __bfloat162float(hi));
    } else if (i < 2048 + 8192) {                 // W3 [64x64]
        int j = i - 6144, o = j >> 6, k = j & 63;
        float w = W3[j] * (g3[o] * rsqrtf(v3[o] + EPS));
        __nv_bfloat16 hi = __float2bfloat16(w);
        int off = 24576 + woff16<4>(o, k);
        *(__nv_bfloat16*)(wbuf + off)     = hi;
        *(__nv_bfloat16*)(wbuf + off + 8) = __float2bfloat16(w - __bfloat162float(hi));
    }
    if (i < 64) {
        bbuf[i]       = b1[i] - m1[i] * (g1[i] * rsqrtf(v1[i] + EPS));
        bbuf[64 + i]  = b2[i] - m2[i] * (g2[i] * rsqrtf(v2[i] + EPS));
        bbuf[128 + i] = b3[i] - m3[i] * (g3[i] * rsqrtf(v3[i] + EPS));
    }
    // PDL: allow the dependent (main) kernel's griddepcontrol.wait to release
    asm volatile("griddepcontrol.launch_dependents;");
}

// One GEMM stage (per warp, one 16-row m-tile), bias pre-loaded into accumulators:
// D[8][4] = bias + (Ah+Al)@(Wh+Wl)^T, dropping lo*lo. One LDS.128 per (j,t).
template<int KT>
__device__ __forceinline__ void run_stage(const char* w, const float* bias,
                                          unsigned Ah[4][4], unsigned Al[4][4],
                                          float D[8][4], int g, int p) {
    #pragma unroll
    for (int j = 0; j < 8; ++j) {
        float b0, b1;
        unpk(*(const ull*)(bias + 8 * j + 2 * p), b0, b1);
        D[j][0] = b0; D[j][1] = b1; D[j][2] = b0; D[j][3] = b1;
        int o = 8 * j + g;
        #pragma unroll
        for (int t = 0; t < KT; ++t) {
            int ts = t ^ (o & (KT - 1));
            int unit = (o * KT + ts) * 4 + p;
            ulonglong2 wv = *(const ulonglong2*)(w + unit * 16);   // one LDS.128: hi|lo
            unsigned bh0 = (unsigned)wv.x, bh1 = (unsigned)(wv.x >> 32);
            unsigned bl0 = (unsigned)wv.y, bl1 = (unsigned)(wv.y >> 32);
            mma16816(D[j], Ah[t], bh0, bh1);   // hi*hi
            mma16816(D[j], Ah[t], bl0, bl1);   // hi*lo
            mma16816(D[j], Al[t], bh0, bh1);   // lo*hi
        }
    }
}

// gelu + re-split into next stage's A fragments (pure per-thread register work)
__device__ __forceinline__ void epilogue_mid(float D[8][4],
                                             unsigned Ah[4][4], unsigned Al[4][4]) {
    #pragma unroll
    for (int j = 0; j < 8; ++j) {
        int t = j >> 1;
        int rb = (j & 1) ? 2 : 0;
        ull v0 = gelu2(pk2(D[j][0], D[j][1]));
        ull v1 = gelu2(pk2(D[j][2], D[j][3]));
        splitpair(v0, Ah[t][rb],     Al[t][rb]);
        splitpair(v1, Ah[t][rb + 1], Al[t][rb + 1]);
    }
}

__global__ void __launch_bounds__(THREADS, 2) mlp_mma_kernel(
    const float* __restrict__ x, float* __restrict__ out)
{
    __shared__ __align__(16) float sbias[256];
    __shared__ __align__(16) char  sw[40960];
    const int tid = threadIdx.x;
    const int lane = tid & 31, wid = tid >> 5;   // warp = one 16-row m-tile
    const int g = lane >> 2, p = lane & 3;

    // ---- PDL phase 1: fold-independent prologue (x LDG + A-fragment build) ----
    const int pbase = blockIdx.x * TILE_M;
    unsigned Ah[4][4], Al[4][4];
    {
        const float* xr = x + (size_t)(pbase + wid * 16 + g) * 32;   // row g; row g+8 = +256
        #pragma unroll
        for (int t = 0; t < 2; ++t) {
            int c0 = p * 2 + t * 16;
            splitpair(*(const ull*)(xr + c0),           Ah[t][0], Al[t][0]);
            splitpair(*(const ull*)(xr + 256 + c0),     Ah[t][1], Al[t][1]);
            splitpair(*(const ull*)(xr + c0 + 8),       Ah[t][2], Al[t][2]);
            splitpair(*(const ull*)(xr + 256 + c0 + 8), Ah[t][3], Al[t][3]);
        }
    }

    // ---- PDL phase 2: wait for fold_kernel's weights, then stage them ----
    asm volatile("griddepcontrol.wait;" ::: "memory");
    {
        const uint4* src = (const uint4*)wbuf;
        uint4* dst = (uint4*)sw;
        #pragma unroll
        for (int i = 0; i < 10; ++i) dst[tid + i * THREADS] = src[tid + i * THREADS];
        if (tid < 48) ((uint4*)sbias)[tid] = ((const uint4*)bbuf)[tid];
    }
    __syncthreads();

    float D[8][4];

    run_stage<2>(sw,         sbias,       Ah, Al, D, g, p);
    epilogue_mid(D, Ah, Al);

    run_stage<4>(sw + 8192,  sbias + 64,  Ah, Al, D, g, p);
    epilogue_mid(D, Ah, Al);

    run_stage<4>(sw + 24576, sbias + 128, Ah, Al, D, g, p);

    // ---- final: gelu -> direct transposed STG (4x32B segments per warp-instr) ----
    float* ob = out + (size_t)(pbase >> 10) * 65536 + (pbase & 1023) + wid * 16 + g;
    #pragma unroll
    for (int j = 0; j < 8; ++j) {
        int o0 = 8 * j + 2 * p;
        ull v0 = gelu2(pk2(D[j][0], D[j][1]));   // cols o0,o0+1 @ row g
        ull v1 = gelu2(pk2(D[j][2], D[j][3]));   // cols o0,o0+1 @ row g+8
        float f0, f1;
        unpk(v0, f0, f1);
        ob[(size_t)o0 * 1024]       = f0;
        ob[(size_t)(o0 + 1) * 1024] = f1;
        unpk(v1, f0, f1);
        ob[(size_t)o0 * 1024 + 8]       = f0;
        ob[(size_t)(o0 + 1) * 1024 + 8] = f1;
    }
}

extern "C" void kernel_launch(void* const* d_in, const int* in_sizes, int n_in,
                              void* d_out, int out_size)
{
    const float* x  = (const float*)d_in[0];
    const float* W1 = (const float*)d_in[1];
    const float* g1 = (const float*)d_in[2];
    const float* b1 = (const float*)d_in[3];
    const float* m1 = (const float*)d_in[4];
    const float* v1 = (const float*)d_in[5];
    const float* W2 = (const float*)d_in[6];
    const float* g2 = (const float*)d_in[7];
    const float* b2 = (const float*)d_in[8];
    const float* m2 = (const float*)d_in[9];
    const float* v2 = (const float*)d_in[10];
    const float* W3 = (const float*)d_in[11];
    const float* g3 = (const float*)d_in[12];
    const float* b3 = (const float*)d_in[13];
    const float* m3 = (const float*)d_in[14];
    const float* v3 = (const float*)d_in[15];
    float* out = (float*)d_out;

    fold_kernel<<<40, 256>>>(W1, g1, b1, m1, v1, W2, g2, b2, m2, v2, W3, g3, b3, m3, v3);

    // Main kernel with programmatic stream serialization: launches while fold runs;
    // griddepcontrol.wait inside gates only the weight reads.
    cudaLaunchConfig_t cfg = {};
    cfg.gridDim = dim3(NBLK, 1, 1);
    cfg.blockDim = dim3(THREADS, 1, 1);
    cfg.dynamicSmemBytes = 0;
    cfg.stream = 0;
    cudaLaunchAttribute attrs[1];
    attrs[0].id = cudaLaunchAttributeProgrammaticStreamSerialization;
    attrs[0].val.programmaticStreamSerializationAllowed = 1;
    cfg.attrs = attrs;
    cfg.numAttrs = 1;
    cudaLaunchKernelEx(&cfg, mlp_mma_kernel, x, (float*)d_out);
}